// round 9
// baseline (speedup 1.0000x reference)
#include <cuda_runtime.h>
#include <math.h>

// Problem dims (fixed by the dataset)
#define B_ 256
#define T_ 32
#define V_ 50257
#define D_ 512

typedef unsigned long long ull;

// ---------------------------------------------------------------------------
// Device-global scratch (static allocations are allowed; cudaMalloc is not)
// ---------------------------------------------------------------------------
__device__ float g_sigs[(size_t)V_ * D_];    // normalized signals for the whole vocab
__device__ float g_signq[V_];                // ||sig_v||^2
__device__ float g_state[2][B_ * D_];        // ping-pong state
__device__ float g_snorm2[B_];               // ||state_b||^2
__device__ float g_negit;                    // -1 / softplus(temperature_raw)
__device__ unsigned g_bar[8];                // per-m-group step barrier counters

// ---------------------------------------------------------------------------
// Packed fp32x2 helpers (Blackwell FFMA2 — only reachable via PTX)
// ---------------------------------------------------------------------------
__device__ __forceinline__ ull pack2(float x, float y) {
    ull r;
    asm("mov.b64 %0, {%1, %2};" : "=l"(r) : "f"(x), "f"(y));
    return r;
}
__device__ __forceinline__ void unpack2(ull v, float& x, float& y) {
    asm("mov.b64 {%0, %1}, %2;" : "=f"(x), "=f"(y) : "l"(v));
}
__device__ __forceinline__ void ffma2(ull& d, ull a, ull b) {
    asm("fma.rn.f32x2 %0, %1, %2, %0;" : "+l"(d) : "l"(a), "l"(b));
}

// ---------------------------------------------------------------------------
// Signals: embedding row -> LayerNorm (no affine, biased var, eps=1e-5) -> L2
// ---------------------------------------------------------------------------
__global__ __launch_bounds__(128) void sig_kernel(const float* __restrict__ emb) {
    const int r = blockIdx.x;
    const int tid = threadIdx.x;
    const float4 x = ((const float4*)(emb + (size_t)r * D_))[tid];

    float s  = (x.x + x.y) + (x.z + x.w);
    float sq = x.x * x.x + x.y * x.y + x.z * x.z + x.w * x.w;
    #pragma unroll
    for (int o = 16; o > 0; o >>= 1) {
        s  += __shfl_down_sync(0xffffffffu, s, o);
        sq += __shfl_down_sync(0xffffffffu, sq, o);
    }
    __shared__ float ws[4], wq[4];
    const int w = tid >> 5, l = tid & 31;
    if (l == 0) { ws[w] = s; wq[w] = sq; }
    __syncthreads();
    s  = (ws[0] + ws[1]) + (ws[2] + ws[3]);
    sq = (wq[0] + wq[1]) + (wq[2] + wq[3]);

    const float mean = s * (1.0f / D_);
    float var = fmaxf(sq * (1.0f / D_) - mean * mean, 0.0f);
    const float rstd = rsqrtf(var + 1e-5f);
    float nrm = fmaxf(sqrtf((float)D_ * var) * rstd, 1e-12f);
    const float scale = rstd / nrm;

    float4 o;
    o.x = (x.x - mean) * scale;
    o.y = (x.y - mean) * scale;
    o.z = (x.z - mean) * scale;
    o.w = (x.w - mean) * scale;
    ((float4*)(g_sigs + (size_t)r * D_))[tid] = o;
    if (tid == 0) g_signq[r] = (float)D_ * var * scale * scale;   // == ||sig||^2
}

__global__ void zero_kernel() {
    const int i = blockIdx.x * 256 + threadIdx.x;
    g_state[0][i] = 0.0f;
    if (blockIdx.x == 0 && threadIdx.x < 8) g_bar[threadIdx.x] = 0u;
}

// ---------------------------------------------------------------------------
// Persistent step kernel: all 960 Euler steps in ONE launch.
// Grid: (16 n-tiles, 8 m-groups) = 128 CTAs, 128 threads, 1 CTA/SM.
// Each CTA keeps its 32-column diffusion slice resident in smem (k-major) for
// the whole kernel; per step it reloads its 32 state rows (L2) packed-dup for
// FFMA2, runs a 32x32x512 GEMM tile + fused cubic/sig/Euler/clip epilogue,
// then syncs its 16-CTA m-group via a monotonic atomic barrier.
// ---------------------------------------------------------------------------
#define SB_OFF   0
#define SAP_OFF  73728                      // 512*36*4
#define WS_OFF   (SAP_OFF + 32 * 514 * 8)   // + 131584
#define SMEAN_OFF (WS_OFF + 128 * 4)
#define STEP_SMEM (SMEAN_OFF + 32 * 4)      // 206720 bytes

__global__ __launch_bounds__(128, 1) void persist_kernel(const float* __restrict__ dif,
                                                         const int* __restrict__ ids) {
    extern __shared__ unsigned char sm[];
    float (*sB)[36]   = (float (*)[36])(sm + SB_OFF);     // [512 k][32 n (+pad)]
    ull   (*sAp)[514] = (ull (*)[514])(sm + SAP_OFF);     // [32 m][512 k] packed (a,a)
    float* wsum  = (float*)(sm + WS_OFF);                 // [32 rows][4 warps]
    float* smean = (float*)(sm + SMEAN_OFF);              // [32]

    const int tid  = threadIdx.x;
    const int tx   = tid & 7;       // 8  -> 4 n each (32 n)
    const int ty   = tid >> 3;      // 16 -> 2 m each (32 m)
    const int w    = tid >> 5, lane = tid & 31;
    const int n0   = blockIdx.x * 32;
    const int mg   = blockIdx.y;
    const int m0   = mg * 32;

    // ---- one-time: resident diffusion slice, k-major ----
    for (int i = tid; i < 32 * 128; i += 128) {           // 32 n-rows x 128 float4
        const int r = i >> 7, c4 = i & 127;
        const float4 v = *(const float4*)(dif + (size_t)(n0 + r) * D_ + c4 * 4);
        sB[c4 * 4 + 0][r] = v.x;
        sB[c4 * 4 + 1][r] = v.y;
        sB[c4 * 4 + 2][r] = v.z;
        sB[c4 * 4 + 3][r] = v.w;
    }
    __syncthreads();

    for (int step = 0; step < 960; step++) {
        const float* __restrict__ src = g_state[step & 1];
        float* __restrict__ dst = g_state[(step + 1) & 1];

        // ---- phase 1: load 32 state rows -> packed smem; fold in row means ----
        float cur = 0.0f;
        #pragma unroll 4
        for (int i = 0; i < 64; i++) {
            const int row = i >> 1;
            const int c2 = ((i & 1) << 7) + tid;          // float2 index in [0,256)
            const float2 v = __ldcg((const float2*)(src + (size_t)(m0 + row) * D_) + c2);
            sAp[row][c2 * 2]     = pack2(v.x, v.x);
            sAp[row][c2 * 2 + 1] = pack2(v.y, v.y);
            cur += v.x + v.y;
            if (i & 1) {   // row complete across the block -> warp partial
                #pragma unroll
                for (int o = 16; o > 0; o >>= 1)
                    cur += __shfl_down_sync(0xffffffffu, cur, o);
                if (lane == 0) wsum[row * 4 + w] = cur;
                cur = 0.0f;
            }
        }
        __syncthreads();
        if (tid < 32)
            smean[tid] = (wsum[tid * 4] + wsum[tid * 4 + 1] +
                          wsum[tid * 4 + 2] + wsum[tid * 4 + 3]) * (1.0f / D_);
        __syncthreads();

        // ---- phase 2: 32x32x512 tile GEMM, micro 2m x 4n, packed FFMA2 ----
        ull acc00 = 0ull, acc01 = 0ull, acc10 = 0ull, acc11 = 0ull;
        const int r0 = ty * 2, r1 = r0 + 1;
        #pragma unroll 8
        for (int kk = 0; kk < D_; kk += 2) {
            const ulonglong2 a0 = *(const ulonglong2*)&sAp[r0][kk];   // {(a,a)_k,(a,a)_k+1}
            const ulonglong2 a1 = *(const ulonglong2*)&sAp[r1][kk];
            const ulonglong2 b0 = *(const ulonglong2*)&sB[kk][tx * 4];
            const ulonglong2 b1 = *(const ulonglong2*)&sB[kk + 1][tx * 4];
            ffma2(acc00, a0.x, b0.x); ffma2(acc01, a0.x, b0.y);
            ffma2(acc10, a1.x, b0.x); ffma2(acc11, a1.x, b0.y);
            ffma2(acc00, a0.y, b1.x); ffma2(acc01, a0.y, b1.y);
            ffma2(acc10, a1.y, b1.x); ffma2(acc11, a1.y, b1.y);
        }

        // ---- phase 3: epilogue (cubic + signal + Euler + nan_to_num + clip) ----
        const int t = step / 30;   // token index
        #pragma unroll
        for (int mi = 0; mi < 2; mi++) {
            const int r = ty * 2 + mi;
            const int b = m0 + r;
            const int id = __ldg(&ids[b * T_ + t]);
            const float4 sg = *(const float4*)(g_sigs + (size_t)id * D_ + n0 + tx * 4);
            const float mean = smean[r];
            float d0, d1, d2, d3;
            if (mi == 0) { unpack2(acc00, d0, d1); unpack2(acc01, d2, d3); }
            else         { unpack2(acc10, d0, d1); unpack2(acc11, d2, d3); }
            float in[4], dum;
            #pragma unroll
            for (int j = 0; j < 4; j++) unpack2(sAp[r][n0 + tx * 4 + j], in[j], dum);
            const float gg[4] = {sg.x, sg.y, sg.z, sg.w};
            const float dd[4] = {d0, d1, d2, d3};
            float4 o;
            float* po = &o.x;
            #pragma unroll
            for (int j = 0; j < 4; j++) {
                const float c = in[j] - mean;
                const float drift = dd[j] + 0.008f * c * c * c + gg[j];
                float v = in[j] + 0.04f * drift;
                if (!isfinite(v)) v = 0.0f;
                po[j] = fminf(fmaxf(v, -80.0f), 80.0f);
            }
            *(float4*)(dst + (size_t)b * D_ + n0 + tx * 4) = o;
        }

        // ---- phase 4: m-group barrier (16 CTAs), release/acquire ----
        __threadfence();
        __syncthreads();
        if (tid == 0) {
            const unsigned target = 16u * (unsigned)(step + 1);
            atomicAdd(&g_bar[mg], 1u);
            while (*(volatile unsigned*)&g_bar[mg] < target) { }
            __threadfence();
        }
        __syncthreads();
    }
}

// ---------------------------------------------------------------------------
// ||state_b||^2 and -1/softplus(temp). One warp per batch row.
// ---------------------------------------------------------------------------
__global__ void snorm_kernel(const float* __restrict__ traw) {
    const int b = blockIdx.x, lane = threadIdx.x;
    const float4* p4 = (const float4*)(g_state[0] + b * D_);
    float s = 0.f;
    #pragma unroll
    for (int j = 0; j < 4; j++) {
        const float4 v = p4[j * 32 + lane];
        s += v.x * v.x + v.y * v.y + v.z * v.z + v.w * v.w;
    }
    #pragma unroll
    for (int o = 16; o > 0; o >>= 1) s += __shfl_down_sync(0xffffffffu, s, o);
    if (lane == 0) g_snorm2[b] = s;
    if (b == 0 && lane == 0) {
        const float x = traw[0];
        float sp = log1pf(expf(x));
        sp = fmaxf(sp, 1e-6f);
        g_negit = -1.0f / sp;
    }
}

// ---------------------------------------------------------------------------
// Logits: out[b,v] = -sqrt(max(||s_b||^2 + ||g_v||^2 - 2 s_b.g_v, 0)) / temp
// Tile: 32m x 64v per CTA, micro 2m x 8v via packed FFMA2.
// ---------------------------------------------------------------------------
__global__ __launch_bounds__(128) void logits_kernel(float* __restrict__ out) {
    __shared__ float sA[32][36];   // state tile [m][k]
    __shared__ float sB[32][68];   // signals tile, k-major [k][v]

    const float* __restrict__ st = g_state[0];
    const int tid = threadIdx.x;
    const int v0 = blockIdx.x * 64;
    const int m0 = blockIdx.y * 32;
    const int tx = tid & 7, ty = tid >> 3;

    ull acc[2][4] = {};

    for (int k0 = 0; k0 < D_; k0 += 32) {
        __syncthreads();
        #pragma unroll
        for (int i = 0; i < 2; i++) {
            const int idx = tid + i * 128;
            const int r = idx >> 3, c = idx & 7;
            *(float4*)&sA[r][c * 4] =
                *(const float4*)(st + (size_t)(m0 + r) * D_ + k0 + c * 4);
        }
        #pragma unroll
        for (int i = 0; i < 4; i++) {
            const int idx = tid + i * 128;
            const int r = idx >> 3, c = idx & 7;
            const int v = v0 + r;
            float4 x = make_float4(0.f, 0.f, 0.f, 0.f);
            if (v < V_) x = *(const float4*)(g_sigs + (size_t)v * D_ + k0 + c * 4);
            sB[c * 4 + 0][r] = x.x;
            sB[c * 4 + 1][r] = x.y;
            sB[c * 4 + 2][r] = x.z;
            sB[c * 4 + 3][r] = x.w;
        }
        __syncthreads();
        #pragma unroll
        for (int kk = 0; kk < 32; kk++) {
            const float a0 = sA[ty * 2 + 0][kk];
            const float a1 = sA[ty * 2 + 1][kk];
            const ull aa0 = pack2(a0, a0);
            const ull aa1 = pack2(a1, a1);
            const ulonglong2 b01 = *(const ulonglong2*)&sB[kk][tx * 8];
            const ulonglong2 b23 = *(const ulonglong2*)&sB[kk][tx * 8 + 4];
            ffma2(acc[0][0], aa0, b01.x); ffma2(acc[0][1], aa0, b01.y);
            ffma2(acc[0][2], aa0, b23.x); ffma2(acc[0][3], aa0, b23.y);
            ffma2(acc[1][0], aa1, b01.x); ffma2(acc[1][1], aa1, b01.y);
            ffma2(acc[1][2], aa1, b23.x); ffma2(acc[1][3], aa1, b23.y);
        }
    }

    const float negit = g_negit;
    #pragma unroll
    for (int mi = 0; mi < 2; mi++) {
        const int b = m0 + ty * 2 + mi;
        const float sn = g_snorm2[b];
        #pragma unroll
        for (int pj = 0; pj < 4; pj++) {
            float d0, d1;
            unpack2(acc[mi][pj], d0, d1);
            const int v = v0 + tx * 8 + pj * 2;
            if (v < V_) {
                const float sq = fmaxf(sn + g_signq[v] - 2.0f * d0, 0.0f);
                out[(size_t)b * V_ + v] = sqrtf(sq) * negit;
            }
            if (v + 1 < V_) {
                const float sq = fmaxf(sn + g_signq[v + 1] - 2.0f * d1, 0.0f);
                out[(size_t)b * V_ + v + 1] = sqrtf(sq) * negit;
            }
        }
    }
}

// ---------------------------------------------------------------------------
// Launch: 5 graph nodes total (tiny graph -> no lingering upload buffer).
// ---------------------------------------------------------------------------
extern "C" void kernel_launch(void* const* d_in, const int* in_sizes, int n_in,
                              void* d_out, int out_size) {
    const int*   ids  = nullptr;
    const float* emb  = nullptr;
    const float* dif  = nullptr;
    const float* traw = nullptr;
    for (int i = 0; i < n_in; i++) {
        switch (in_sizes[i]) {
            case B_ * T_:  ids  = (const int*)d_in[i];   break;
            case V_ * D_:  emb  = (const float*)d_in[i]; break;
            case D_ * D_:  dif  = (const float*)d_in[i]; break;
            case 1:        traw = (const float*)d_in[i]; break;
        }
    }
    float* out = (float*)d_out;

    static bool attr_set = false;
    if (!attr_set) {
        cudaFuncSetAttribute(persist_kernel,
                             cudaFuncAttributeMaxDynamicSharedMemorySize, STEP_SMEM);
        attr_set = true;
    }

    sig_kernel<<<V_, 128>>>(emb);
    zero_kernel<<<(B_ * D_) / 256, 256>>>();
    persist_kernel<<<dim3(16, 8), 128, STEP_SMEM>>>(dif, ids);
    snorm_kernel<<<B_, 32>>>(traw);
    logits_kernel<<<dim3((V_ + 63) / 64, B_ / 32), 128>>>(out);
    (void)out_size;
}

// round 10
// speedup vs baseline: 1.6154x; 1.6154x over previous
#include <cuda_runtime.h>
#include <math.h>

// Problem dims (fixed by the dataset)
#define B_ 256
#define T_ 32
#define V_ 50257
#define D_ 512

typedef unsigned long long ull;

// ---------------------------------------------------------------------------
// Device-global scratch (static allocations are allowed; cudaMalloc is not)
// ---------------------------------------------------------------------------
__device__ float g_sigs[(size_t)V_ * D_];    // normalized signals for the whole vocab
__device__ float g_signq[V_];                // ||sig_v||^2
__device__ float g_state[2][B_ * D_];        // ping-pong state
__device__ float g_snorm2[B_];               // ||state_b||^2
__device__ float g_negit;                    // -1 / softplus(temperature_raw)
__device__ unsigned g_bar[8];                // per-m-group step barrier counters

// ---------------------------------------------------------------------------
// Packed fp32x2 helpers (Blackwell FFMA2/FADD2 — only reachable via PTX)
// ---------------------------------------------------------------------------
__device__ __forceinline__ ull pack2(float x, float y) {
    ull r;
    asm("mov.b64 %0, {%1, %2};" : "=l"(r) : "f"(x), "f"(y));
    return r;
}
__device__ __forceinline__ void unpack2(ull v, float& x, float& y) {
    asm("mov.b64 {%0, %1}, %2;" : "=f"(x), "=f"(y) : "l"(v));
}
__device__ __forceinline__ void ffma2(ull& d, ull a, ull b) {
    asm("fma.rn.f32x2 %0, %1, %2, %0;" : "+l"(d) : "l"(a), "l"(b));
}
__device__ __forceinline__ ull add2(ull a, ull b) {
    ull r;
    asm("add.rn.f32x2 %0, %1, %2;" : "=l"(r) : "l"(a), "l"(b));
    return r;
}

// ---------------------------------------------------------------------------
// Signals: embedding row -> LayerNorm (no affine, biased var, eps=1e-5) -> L2
// ---------------------------------------------------------------------------
__global__ __launch_bounds__(128) void sig_kernel(const float* __restrict__ emb) {
    const int r = blockIdx.x;
    const int tid = threadIdx.x;
    const float4 x = ((const float4*)(emb + (size_t)r * D_))[tid];

    float s  = (x.x + x.y) + (x.z + x.w);
    float sq = x.x * x.x + x.y * x.y + x.z * x.z + x.w * x.w;
    #pragma unroll
    for (int o = 16; o > 0; o >>= 1) {
        s  += __shfl_down_sync(0xffffffffu, s, o);
        sq += __shfl_down_sync(0xffffffffu, sq, o);
    }
    __shared__ float ws[4], wq[4];
    const int w = tid >> 5, l = tid & 31;
    if (l == 0) { ws[w] = s; wq[w] = sq; }
    __syncthreads();
    s  = (ws[0] + ws[1]) + (ws[2] + ws[3]);
    sq = (wq[0] + wq[1]) + (wq[2] + wq[3]);

    const float mean = s * (1.0f / D_);
    float var = fmaxf(sq * (1.0f / D_) - mean * mean, 0.0f);
    const float rstd = rsqrtf(var + 1e-5f);
    float nrm = fmaxf(sqrtf((float)D_ * var) * rstd, 1e-12f);
    const float scale = rstd / nrm;

    float4 o;
    o.x = (x.x - mean) * scale;
    o.y = (x.y - mean) * scale;
    o.z = (x.z - mean) * scale;
    o.w = (x.w - mean) * scale;
    ((float4*)(g_sigs + (size_t)r * D_))[tid] = o;
    if (tid == 0) g_signq[r] = (float)D_ * var * scale * scale;   // == ||sig||^2
}

__global__ void zero_kernel() {
    const int i = blockIdx.x * 256 + threadIdx.x;
    g_state[0][i] = 0.0f;
    if (blockIdx.x == 0 && threadIdx.x < 8) g_bar[threadIdx.x] = 0u;
}

// ---------------------------------------------------------------------------
// Persistent step kernel: all 960 Euler steps in ONE launch.
// Grid (16 n-tiles, 8 m-groups) = 128 CTAs, 256 threads, 1 CTA/SM.
//
// FFMA2 pairs run along m: accumulators hold (row m0, row m1). A (state) is
// stored k-major [k][m] so an m-pair loads as a natural 8-byte pair (no dup,
// no packing). B (diffusion slice) is loop-invariant: duplicated (b,b) ONCE
// into smem at kernel start. 4-way k-split across warp pairs; smem partial
// reduction; fused cubic/sig/Euler/nan/clip epilogue; monotonic 16-CTA
// m-group barrier between steps.
// ---------------------------------------------------------------------------
#define SBD_OFF   0                                   // ull [512][32]   131072 B
#define SA_OFF    131072                              // float [512][33]  67584 B
#define PART_OFF  (SA_OFF + 512 * 33 * 4)             // ull [4][16*33]   16896 B
#define SMEAN_OFF (PART_OFF + 4 * 528 * 8)            // float [32]
#define STEP_SMEM (SMEAN_OFF + 128)                   // 215680 B

__global__ __launch_bounds__(256, 1) void persist_kernel(const float* __restrict__ dif,
                                                         const int* __restrict__ ids) {
    extern __shared__ unsigned char sm[];
    ull*   sBd   = (ull*)(sm + SBD_OFF);      // [k][32 n] dup (b,b)
    float* sA    = (float*)(sm + SA_OFF);     // [k][32 m] stride 33 (conflict-free)
    ull*   part  = (ull*)(sm + PART_OFF);     // [g][16 mp (stride 33)][32 n]
    float* smean = (float*)(sm + SMEAN_OFF);  // [32]

    const int tid = threadIdx.x;
    const int n0  = blockIdx.x * 32;
    const int mg  = blockIdx.y;
    const int m0  = mg * 32;

    // ---- one-time: duplicate diffusion slice into sBd, k-major ----
    {
        const int n = tid >> 3, j = tid & 7;
        const float* drow = dif + (size_t)(n0 + n) * D_;
        #pragma unroll
        for (int i = 0; i < 16; i++) {
            const int k4 = i * 8 + j;
            const float4 v = *(const float4*)(drow + k4 * 4);
            sBd[(k4 * 4 + 0) * 32 + n] = pack2(v.x, v.x);
            sBd[(k4 * 4 + 1) * 32 + n] = pack2(v.y, v.y);
            sBd[(k4 * 4 + 2) * 32 + n] = pack2(v.z, v.z);
            sBd[(k4 * 4 + 3) * 32 + n] = pack2(v.w, v.w);
        }
    }
    __syncthreads();

    // GEMM thread mapping: 4 k-groups x (4 tx n-octs x 16 tyy m-pairs)
    const int g    = tid >> 6;           // k-group (128 k each)
    const int lcl  = tid & 63;
    const int tx   = lcl >> 4;           // n-oct: n = tx*8 + jj
    const int tyy  = lcl & 15;           // m-pair: rows 2*tyy, 2*tyy+1
    const int kbeg = g * 128;

    // phase-1 mapping: 32 rows x 8 k-slices
    const int pm = tid >> 3, pj = tid & 7;

    // epilogue mapping: 16 m-pairs x 16 n-pairs
    const int emp = tid >> 4;
    const int en  = (tid & 15) * 2;

    for (int step = 0; step < 960; step++) {
        const float* __restrict__ src = g_state[step & 1];
        float* __restrict__ dst = g_state[(step + 1) & 1];

        // ---- phase 1: state rows -> sA (k-major) + row means ----
        {
            const float* srow = src + (size_t)(m0 + pm) * D_;
            float s = 0.f;
            #pragma unroll
            for (int i = 0; i < 16; i++) {
                const int k4 = i * 8 + pj;
                const float4 v = __ldcg((const float4*)srow + k4);
                const int k = k4 * 4;
                sA[(k + 0) * 33 + pm] = v.x;
                sA[(k + 1) * 33 + pm] = v.y;
                sA[(k + 2) * 33 + pm] = v.z;
                sA[(k + 3) * 33 + pm] = v.w;
                s += (v.x + v.y) + (v.z + v.w);
            }
            s += __shfl_down_sync(0xffffffffu, s, 4, 8);
            s += __shfl_down_sync(0xffffffffu, s, 2, 8);
            s += __shfl_down_sync(0xffffffffu, s, 1, 8);
            if (pj == 0) smean[pm] = s * (1.0f / D_);
        }
        __syncthreads();

        // ---- phase 2: GEMM partial over this warp-pair's 128 k ----
        ull a0 = 0, a1 = 0, a2 = 0, a3 = 0, a4 = 0, a5 = 0, a6 = 0, a7 = 0;
        {
            const float* sAp = sA + tyy * 2;
            const ull* sBp = sBd + tx * 8;
            #pragma unroll 4
            for (int kk = kbeg; kk < kbeg + 128; kk++) {
                const ull ap = pack2(sAp[kk * 33], sAp[kk * 33 + 1]);
                const ull* br = sBp + kk * 32;
                const ulonglong2 b0 = *(const ulonglong2*)(br);
                const ulonglong2 b1 = *(const ulonglong2*)(br + 2);
                const ulonglong2 b2 = *(const ulonglong2*)(br + 4);
                const ulonglong2 b3 = *(const ulonglong2*)(br + 6);
                ffma2(a0, ap, b0.x); ffma2(a1, ap, b0.y);
                ffma2(a2, ap, b1.x); ffma2(a3, ap, b1.y);
                ffma2(a4, ap, b2.x); ffma2(a5, ap, b2.y);
                ffma2(a6, ap, b3.x); ffma2(a7, ap, b3.y);
            }
            ull* p = part + g * 528 + tyy * 33 + tx * 8;
            p[0] = a0; p[1] = a1; p[2] = a2; p[3] = a3;
            p[4] = a4; p[5] = a5; p[6] = a6; p[7] = a7;
        }
        __syncthreads();

        // ---- phase 3: k-split reduction + fused epilogue ----
        {
            const int t = step / 30;
            const ull* pb = part + emp * 33 + en;
            ull s0 = add2(add2(pb[0], pb[528]), add2(pb[1056], pb[1584]));
            ull s1 = add2(add2(pb[1], pb[529]), add2(pb[1057], pb[1585]));
            float d00, d10, d01, d11;
            unpack2(s0, d00, d10);     // (row m0, row m1) at col en
            unpack2(s1, d01, d11);     // at col en+1

            const int dgl = n0 + en;
            const float in00 = sA[dgl * 33 + emp * 2];
            const float in10 = sA[dgl * 33 + emp * 2 + 1];
            const float in01 = sA[(dgl + 1) * 33 + emp * 2];
            const float in11 = sA[(dgl + 1) * 33 + emp * 2 + 1];
            const float mean0 = smean[emp * 2];
            const float mean1 = smean[emp * 2 + 1];

            const int b0 = m0 + emp * 2, b1 = b0 + 1;
            const int id0 = __ldg(&ids[b0 * T_ + t]);
            const int id1 = __ldg(&ids[b1 * T_ + t]);
            const float2 sg0 = *(const float2*)(g_sigs + (size_t)id0 * D_ + dgl);
            const float2 sg1 = *(const float2*)(g_sigs + (size_t)id1 * D_ + dgl);

            const float in_[4] = {in00, in01, in10, in11};
            const float dd_[4] = {d00, d01, d10, d11};
            const float sg_[4] = {sg0.x, sg0.y, sg1.x, sg1.y};
            const float mn_[4] = {mean0, mean0, mean1, mean1};
            float o_[4];
            #pragma unroll
            for (int j = 0; j < 4; j++) {
                const float c = in_[j] - mn_[j];
                const float drift = dd_[j] + 0.008f * c * c * c + sg_[j];
                float v = in_[j] + 0.04f * drift;
                if (!isfinite(v)) v = 0.0f;
                o_[j] = fminf(fmaxf(v, -80.0f), 80.0f);
            }
            *(float2*)(dst + (size_t)b0 * D_ + dgl) = make_float2(o_[0], o_[1]);
            *(float2*)(dst + (size_t)b1 * D_ + dgl) = make_float2(o_[2], o_[3]);
        }

        // ---- phase 4: m-group barrier (16 CTAs) ----
        __syncthreads();
        if (tid == 0) {
            __threadfence();
            atomicAdd(&g_bar[mg], 1u);
            const unsigned target = 16u * (unsigned)(step + 1);
            while (*(volatile unsigned*)&g_bar[mg] < target) { }
            __threadfence();
        }
        __syncthreads();
    }
}

// ---------------------------------------------------------------------------
// ||state_b||^2 and -1/softplus(temp). One warp per batch row.
// ---------------------------------------------------------------------------
__global__ void snorm_kernel(const float* __restrict__ traw) {
    const int b = blockIdx.x, lane = threadIdx.x;
    const float4* p4 = (const float4*)(g_state[0] + b * D_);
    float s = 0.f;
    #pragma unroll
    for (int j = 0; j < 4; j++) {
        const float4 v = p4[j * 32 + lane];
        s += v.x * v.x + v.y * v.y + v.z * v.z + v.w * v.w;
    }
    #pragma unroll
    for (int o = 16; o > 0; o >>= 1) s += __shfl_down_sync(0xffffffffu, s, o);
    if (lane == 0) g_snorm2[b] = s;
    if (b == 0 && lane == 0) {
        const float x = traw[0];
        float sp = log1pf(expf(x));
        sp = fmaxf(sp, 1e-6f);
        g_negit = -1.0f / sp;
    }
}

// ---------------------------------------------------------------------------
// Logits: out[b,v] = -sqrt(max(||s_b||^2 + ||g_v||^2 - 2 s_b.g_v, 0)) / temp
// Tile: 32m x 64v per CTA, micro 2m x 8v via packed FFMA2.
// ---------------------------------------------------------------------------
__global__ __launch_bounds__(128) void logits_kernel(float* __restrict__ out) {
    __shared__ float sA[32][36];   // state tile [m][k]
    __shared__ float sB[32][68];   // signals tile, k-major [k][v]

    const float* __restrict__ st = g_state[0];
    const int tid = threadIdx.x;
    const int v0 = blockIdx.x * 64;
    const int m0 = blockIdx.y * 32;
    const int tx = tid & 7, ty = tid >> 3;

    ull acc[2][4] = {};

    for (int k0 = 0; k0 < D_; k0 += 32) {
        __syncthreads();
        #pragma unroll
        for (int i = 0; i < 2; i++) {
            const int idx = tid + i * 128;
            const int r = idx >> 3, c = idx & 7;
            *(float4*)&sA[r][c * 4] =
                *(const float4*)(st + (size_t)(m0 + r) * D_ + k0 + c * 4);
        }
        #pragma unroll
        for (int i = 0; i < 4; i++) {
            const int idx = tid + i * 128;
            const int r = idx >> 3, c = idx & 7;
            const int v = v0 + r;
            float4 x = make_float4(0.f, 0.f, 0.f, 0.f);
            if (v < V_) x = *(const float4*)(g_sigs + (size_t)v * D_ + k0 + c * 4);
            sB[c * 4 + 0][r] = x.x;
            sB[c * 4 + 1][r] = x.y;
            sB[c * 4 + 2][r] = x.z;
            sB[c * 4 + 3][r] = x.w;
        }
        __syncthreads();
        #pragma unroll
        for (int kk = 0; kk < 32; kk++) {
            const float a0 = sA[ty * 2 + 0][kk];
            const float a1 = sA[ty * 2 + 1][kk];
            const ull aa0 = pack2(a0, a0);
            const ull aa1 = pack2(a1, a1);
            const ulonglong2 b01 = *(const ulonglong2*)&sB[kk][tx * 8];
            const ulonglong2 b23 = *(const ulonglong2*)&sB[kk][tx * 8 + 4];
            ffma2(acc[0][0], aa0, b01.x); ffma2(acc[0][1], aa0, b01.y);
            ffma2(acc[0][2], aa0, b23.x); ffma2(acc[0][3], aa0, b23.y);
            ffma2(acc[1][0], aa1, b01.x); ffma2(acc[1][1], aa1, b01.y);
            ffma2(acc[1][2], aa1, b23.x); ffma2(acc[1][3], aa1, b23.y);
        }
    }

    const float negit = g_negit;
    #pragma unroll
    for (int mi = 0; mi < 2; mi++) {
        const int b = m0 + ty * 2 + mi;
        const float sn = g_snorm2[b];
        #pragma unroll
        for (int pj = 0; pj < 4; pj++) {
            float d0, d1;
            unpack2(acc[mi][pj], d0, d1);
            const int v = v0 + tx * 8 + pj * 2;
            if (v < V_) {
                const float sq = fmaxf(sn + g_signq[v] - 2.0f * d0, 0.0f);
                out[(size_t)b * V_ + v] = sqrtf(sq) * negit;
            }
            if (v + 1 < V_) {
                const float sq = fmaxf(sn + g_signq[v + 1] - 2.0f * d1, 0.0f);
                out[(size_t)b * V_ + v + 1] = sqrtf(sq) * negit;
            }
        }
    }
}

// ---------------------------------------------------------------------------
// Launch: 5 graph nodes total.
// ---------------------------------------------------------------------------
extern "C" void kernel_launch(void* const* d_in, const int* in_sizes, int n_in,
                              void* d_out, int out_size) {
    const int*   ids  = nullptr;
    const float* emb  = nullptr;
    const float* dif  = nullptr;
    const float* traw = nullptr;
    for (int i = 0; i < n_in; i++) {
        switch (in_sizes[i]) {
            case B_ * T_:  ids  = (const int*)d_in[i];   break;
            case V_ * D_:  emb  = (const float*)d_in[i]; break;
            case D_ * D_:  dif  = (const float*)d_in[i]; break;
            case 1:        traw = (const float*)d_in[i]; break;
        }
    }
    float* out = (float*)d_out;

    static bool attr_set = false;
    if (!attr_set) {
        cudaFuncSetAttribute(persist_kernel,
                             cudaFuncAttributeMaxDynamicSharedMemorySize, STEP_SMEM);
        attr_set = true;
    }

    sig_kernel<<<V_, 128>>>(emb);
    zero_kernel<<<(B_ * D_) / 256, 256>>>();
    persist_kernel<<<dim3(16, 8), 256, STEP_SMEM>>>(dif, ids);
    snorm_kernel<<<B_, 32>>>(traw);
    logits_kernel<<<dim3((V_ + 63) / 64, B_ / 32), 128>>>(out);
    (void)out_size;
}

// round 11
// speedup vs baseline: 1.7881x; 1.1069x over previous
#include <cuda_runtime.h>
#include <math.h>

// Problem dims (fixed by the dataset)
#define B_ 256
#define T_ 32
#define V_ 50257
#define D_ 512

typedef unsigned long long ull;

// ---------------------------------------------------------------------------
// Device-global scratch (static allocations are allowed; cudaMalloc is not)
// ---------------------------------------------------------------------------
__device__ float g_sigs[(size_t)V_ * D_];    // normalized signals for the whole vocab
__device__ float g_signq[V_];                // ||sig_v||^2
__device__ float g_state[2][B_ * D_];        // ping-pong state
__device__ float g_snorm2[B_];               // ||state_b||^2
__device__ float g_negit;                    // -1 / softplus(temperature_raw)
__device__ unsigned g_bar[16];               // per-m-group step barrier counters

// ---------------------------------------------------------------------------
// Packed fp32x2 helpers (Blackwell FFMA2/FADD2 — only reachable via PTX)
// ---------------------------------------------------------------------------
__device__ __forceinline__ ull pack2(float x, float y) {
    ull r;
    asm("mov.b64 %0, {%1, %2};" : "=l"(r) : "f"(x), "f"(y));
    return r;
}
__device__ __forceinline__ void unpack2(ull v, float& x, float& y) {
    asm("mov.b64 {%0, %1}, %2;" : "=f"(x), "=f"(y) : "l"(v));
}
__device__ __forceinline__ void ffma2(ull& d, ull a, ull b) {
    asm("fma.rn.f32x2 %0, %1, %2, %0;" : "+l"(d) : "l"(a), "l"(b));
}
__device__ __forceinline__ ull add2(ull a, ull b) {
    ull r;
    asm("add.rn.f32x2 %0, %1, %2;" : "=l"(r) : "l"(a), "l"(b));
    return r;
}

// ---------------------------------------------------------------------------
// Signals: embedding row -> LayerNorm (no affine, biased var, eps=1e-5) -> L2
// ---------------------------------------------------------------------------
__global__ __launch_bounds__(128) void sig_kernel(const float* __restrict__ emb) {
    const int r = blockIdx.x;
    const int tid = threadIdx.x;
    const float4 x = ((const float4*)(emb + (size_t)r * D_))[tid];

    float s  = (x.x + x.y) + (x.z + x.w);
    float sq = x.x * x.x + x.y * x.y + x.z * x.z + x.w * x.w;
    #pragma unroll
    for (int o = 16; o > 0; o >>= 1) {
        s  += __shfl_down_sync(0xffffffffu, s, o);
        sq += __shfl_down_sync(0xffffffffu, sq, o);
    }
    __shared__ float ws[4], wq[4];
    const int w = tid >> 5, l = tid & 31;
    if (l == 0) { ws[w] = s; wq[w] = sq; }
    __syncthreads();
    s  = (ws[0] + ws[1]) + (ws[2] + ws[3]);
    sq = (wq[0] + wq[1]) + (wq[2] + wq[3]);

    const float mean = s * (1.0f / D_);
    float var = fmaxf(sq * (1.0f / D_) - mean * mean, 0.0f);
    const float rstd = rsqrtf(var + 1e-5f);
    float nrm = fmaxf(sqrtf((float)D_ * var) * rstd, 1e-12f);
    const float scale = rstd / nrm;

    float4 o;
    o.x = (x.x - mean) * scale;
    o.y = (x.y - mean) * scale;
    o.z = (x.z - mean) * scale;
    o.w = (x.w - mean) * scale;
    ((float4*)(g_sigs + (size_t)r * D_))[tid] = o;
    if (tid == 0) g_signq[r] = (float)D_ * var * scale * scale;   // == ||sig||^2
}

__global__ void zero_kernel() {
    const int i = blockIdx.x * 256 + threadIdx.x;
    g_state[0][i] = 0.0f;
    if (blockIdx.x == 0 && threadIdx.x < 16) g_bar[threadIdx.x] = 0u;
}

// ---------------------------------------------------------------------------
// Persistent step kernel: all 960 Euler steps in ONE launch.
// Grid (8 n-tiles x 16 m-groups) = 128 CTAs, 512 threads, 1 CTA/SM.
//
// CTA tile: 16m x 64n x 512k. FFMA2 pairs run along n: B (diffusion slice,
// loop-invariant) is stored k-major float [k][68] ONCE; natural adjacent-n
// pairs load as LDS.128 with a split-n (tx*4 | tx*4+32) pattern that keeps
// all 32 banks distinct. A (state) is row-major [16][516]: phase 1 is a
// coalesced LDG.128->STS.128 copy, and the GEMM hoists 4 k's of A per
// LDS.128. 8-way k-split across warps; smem partial reduction; fused
// cubic/sig/Euler/nan/clip epilogue; 8-CTA m-group barrier between steps.
// ---------------------------------------------------------------------------
#define SB_OFF    0                              // float [512][68]  139264 B
#define SA_OFF    139264                         // float [16][516]   33024 B
#define PART_OFF  (SA_OFF + 16 * 516 * 4)        // ull  [8][512]     32768 B
#define PMEAN_OFF (PART_OFF + 8 * 512 * 8)       // float [16][36]     2304 B
#define SMEAN_OFF (PMEAN_OFF + 16 * 36 * 4)      // float [16]
#define STEP_SMEM (SMEAN_OFF + 64)               // 207424 B

__global__ __launch_bounds__(512, 1) void persist_kernel(const float* __restrict__ dif,
                                                         const int* __restrict__ ids) {
    extern __shared__ unsigned char sm[];
    float* sB    = (float*)(sm + SB_OFF);     // [k][68] (64 n + pad)
    float* sA    = (float*)(sm + SA_OFF);     // [16 m][516] full rows
    ull*   part  = (ull*)(sm + PART_OFF);     // [8 g][512 pairs]
    float* pmean = (float*)(sm + PMEAN_OFF);  // [16 m][36]
    float* smean = (float*)(sm + SMEAN_OFF);  // [16]

    const int tid = threadIdx.x;
    const int n0  = blockIdx.x * 64;
    const int mg  = blockIdx.y;
    const int m0  = mg * 16;

    // ---- one-time: diffusion slice k-major into sB ----
    {
        const int n = tid >> 3, q = tid & 7;
        const float* drow = dif + (size_t)(n0 + n) * D_;
        #pragma unroll
        for (int i = 0; i < 16; i++) {
            const int k4 = q * 16 + i;
            const float4 v = *(const float4*)(drow + k4 * 4);
            sB[(k4 * 4 + 0) * 68 + n] = v.x;
            sB[(k4 * 4 + 1) * 68 + n] = v.y;
            sB[(k4 * 4 + 2) * 68 + n] = v.z;
            sB[(k4 * 4 + 3) * 68 + n] = v.w;
        }
    }
    __syncthreads();

    // GEMM mapping: 8 k-groups (64 k each) x (8 tx n-slices x 8 tmy m-pairs)
    const int g   = tid >> 6;
    const int lcl = tid & 63;
    const int tx  = lcl & 7;
    const int tmy = lcl >> 3;

    // phase-1 mapping: 16 rows x 32 float4-lanes
    const int pm = tid >> 5, pl = tid & 31;

    // epilogue mapping: pair id = tid; m = tid>>5, np = tid&31 (n = 2*np)
    const int em = tid >> 5;
    const int enp = tid & 31;

    for (int step = 0; step < 960; step++) {
        const float* __restrict__ src = g_state[step & 1];
        float* __restrict__ dst = g_state[(step + 1) & 1];

        // ---- phase 1: coalesced copy of 16 state rows + mean partials ----
        {
            const float4* srow = (const float4*)(src + (size_t)(m0 + pm) * D_);
            float4* arow = (float4*)(sA + pm * 516);
            float s = 0.f;
            #pragma unroll
            for (int j = 0; j < 4; j++) {
                const float4 v = __ldcg(srow + pl + 32 * j);
                arow[pl + 32 * j] = v;
                s += (v.x + v.y) + (v.z + v.w);
            }
            pmean[pm * 36 + pl] = s;
        }
        __syncthreads();

        // means: 16 threads, each reduces one row's 32 partials
        if (tid < 16) {
            const float4* pr = (const float4*)(pmean + tid * 36);
            float4 a = pr[0];
            #pragma unroll
            for (int j = 1; j < 8; j++) {
                const float4 b = pr[j];
                a.x += b.x; a.y += b.y; a.z += b.z; a.w += b.w;
            }
            smean[tid] = ((a.x + a.y) + (a.z + a.w)) * (1.0f / D_);
        }

        // ---- phase 2: GEMM partial over this warp's 64 k ----
        {
            const float* Ar0 = sA + (2 * tmy) * 516;
            const float* Ar1 = Ar0 + 516;
            const float* Bp  = sB + tx * 4;
            ull a0 = 0, a1 = 0, a2 = 0, a3 = 0, a4 = 0, a5 = 0, a6 = 0, a7 = 0;
            const int kend = g * 64 + 64;
            #pragma unroll 4
            for (int kk = g * 64; kk < kend; kk += 4) {
                const float4 av0 = *(const float4*)(Ar0 + kk);
                const float4 av1 = *(const float4*)(Ar1 + kk);
                #pragma unroll
                for (int u = 0; u < 4; u++) {
                    const float s0 = (&av0.x)[u], s1 = (&av1.x)[u];
                    const ull A0 = pack2(s0, s0);
                    const ull A1 = pack2(s1, s1);
                    const float* br = Bp + (kk + u) * 68;
                    const ulonglong2 bl = *(const ulonglong2*)(br);
                    const ulonglong2 bh = *(const ulonglong2*)(br + 32);
                    ffma2(a0, A0, bl.x); ffma2(a1, A0, bl.y);
                    ffma2(a2, A0, bh.x); ffma2(a3, A0, bh.y);
                    ffma2(a4, A1, bl.x); ffma2(a5, A1, bl.y);
                    ffma2(a6, A1, bh.x); ffma2(a7, A1, bh.y);
                }
            }
            // pair flat id = m*32 + np;  np = tx*2 (+1) and tx*2+16 (+17)
            ull* p0 = part + g * 512 + (2 * tmy) * 32 + tx * 2;
            p0[0]  = a0; p0[1]  = a1; p0[16] = a2; p0[17] = a3;
            ull* p1 = p0 + 32;
            p1[0]  = a4; p1[1]  = a5; p1[16] = a6; p1[17] = a7;
        }
        __syncthreads();

        // ---- phase 3: k-split reduction + fused epilogue (2 outputs/thread) ----
        {
            const int t = step / 30;
            const ull* pb = part + em * 32 + enp;
            ull s = add2(add2(pb[0], pb[512]), add2(pb[1024], pb[1536]));
            s = add2(s, add2(add2(pb[2048], pb[2560]), add2(pb[3072], pb[3584])));
            float d0, d1;
            unpack2(s, d0, d1);

            const int dgl = n0 + 2 * enp;
            const float2 iv = *(const float2*)(sA + em * 516 + dgl);
            const float mean = smean[em];
            const int b = m0 + em;
            const int id = __ldg(&ids[b * T_ + t]);
            const float2 sg = *(const float2*)(g_sigs + (size_t)id * D_ + dgl);

            const float in_[2] = {iv.x, iv.y};
            const float dd_[2] = {d0, d1};
            const float sg_[2] = {sg.x, sg.y};
            float o_[2];
            #pragma unroll
            for (int j = 0; j < 2; j++) {
                const float c = in_[j] - mean;
                const float drift = dd_[j] + 0.008f * c * c * c + sg_[j];
                float v = in_[j] + 0.04f * drift;
                if (!isfinite(v)) v = 0.0f;
                o_[j] = fminf(fmaxf(v, -80.0f), 80.0f);
            }
            *(float2*)(dst + (size_t)b * D_ + dgl) = make_float2(o_[0], o_[1]);
        }

        // ---- phase 4: m-group barrier (8 CTAs) ----
        __syncthreads();
        if (tid == 0) {
            __threadfence();
            atomicAdd(&g_bar[mg], 1u);
            const unsigned target = 8u * (unsigned)(step + 1);
            while (*(volatile unsigned*)&g_bar[mg] < target) { }
            __threadfence();
        }
        __syncthreads();
    }
}

// ---------------------------------------------------------------------------
// ||state_b||^2 and -1/softplus(temp). One warp per batch row.
// ---------------------------------------------------------------------------
__global__ void snorm_kernel(const float* __restrict__ traw) {
    const int b = blockIdx.x, lane = threadIdx.x;
    const float4* p4 = (const float4*)(g_state[0] + b * D_);
    float s = 0.f;
    #pragma unroll
    for (int j = 0; j < 4; j++) {
        const float4 v = p4[j * 32 + lane];
        s += v.x * v.x + v.y * v.y + v.z * v.z + v.w * v.w;
    }
    #pragma unroll
    for (int o = 16; o > 0; o >>= 1) s += __shfl_down_sync(0xffffffffu, s, o);
    if (lane == 0) g_snorm2[b] = s;
    if (b == 0 && lane == 0) {
        const float x = traw[0];
        float sp = log1pf(expf(x));
        sp = fmaxf(sp, 1e-6f);
        g_negit = -1.0f / sp;
    }
}

// ---------------------------------------------------------------------------
// Logits: out[b,v] = -sqrt(max(||s_b||^2 + ||g_v||^2 - 2 s_b.g_v, 0)) / temp
// Tile: 32m x 64v per CTA, micro 2m x 8v via packed FFMA2.
// ---------------------------------------------------------------------------
__global__ __launch_bounds__(128) void logits_kernel(float* __restrict__ out) {
    __shared__ float sA[32][36];   // state tile [m][k]
    __shared__ float sB[32][68];   // signals tile, k-major [k][v]

    const float* __restrict__ st = g_state[0];
    const int tid = threadIdx.x;
    const int v0 = blockIdx.x * 64;
    const int m0 = blockIdx.y * 32;
    const int tx = tid & 7, ty = tid >> 3;

    ull acc[2][4] = {};

    for (int k0 = 0; k0 < D_; k0 += 32) {
        __syncthreads();
        #pragma unroll
        for (int i = 0; i < 2; i++) {
            const int idx = tid + i * 128;
            const int r = idx >> 3, c = idx & 7;
            *(float4*)&sA[r][c * 4] =
                *(const float4*)(st + (size_t)(m0 + r) * D_ + k0 + c * 4);
        }
        #pragma unroll
        for (int i = 0; i < 4; i++) {
            const int idx = tid + i * 128;
            const int r = idx >> 3, c = idx & 7;
            const int v = v0 + r;
            float4 x = make_float4(0.f, 0.f, 0.f, 0.f);
            if (v < V_) x = *(const float4*)(g_sigs + (size_t)v * D_ + k0 + c * 4);
            sB[c * 4 + 0][r] = x.x;
            sB[c * 4 + 1][r] = x.y;
            sB[c * 4 + 2][r] = x.z;
            sB[c * 4 + 3][r] = x.w;
        }
        __syncthreads();
        #pragma unroll
        for (int kk = 0; kk < 32; kk++) {
            const float a0 = sA[ty * 2 + 0][kk];
            const float a1 = sA[ty * 2 + 1][kk];
            const ull aa0 = pack2(a0, a0);
            const ull aa1 = pack2(a1, a1);
            const ulonglong2 b01 = *(const ulonglong2*)&sB[kk][tx * 8];
            const ulonglong2 b23 = *(const ulonglong2*)&sB[kk][tx * 8 + 4];
            ffma2(acc[0][0], aa0, b01.x); ffma2(acc[0][1], aa0, b01.y);
            ffma2(acc[0][2], aa0, b23.x); ffma2(acc[0][3], aa0, b23.y);
            ffma2(acc[1][0], aa1, b01.x); ffma2(acc[1][1], aa1, b01.y);
            ffma2(acc[1][2], aa1, b23.x); ffma2(acc[1][3], aa1, b23.y);
        }
    }

    const float negit = g_negit;
    #pragma unroll
    for (int mi = 0; mi < 2; mi++) {
        const int b = m0 + ty * 2 + mi;
        const float sn = g_snorm2[b];
        #pragma unroll
        for (int pj = 0; pj < 4; pj++) {
            float d0, d1;
            unpack2(acc[mi][pj], d0, d1);
            const int v = v0 + tx * 8 + pj * 2;
            if (v < V_) {
                const float sq = fmaxf(sn + g_signq[v] - 2.0f * d0, 0.0f);
                out[(size_t)b * V_ + v] = sqrtf(sq) * negit;
            }
            if (v + 1 < V_) {
                const float sq = fmaxf(sn + g_signq[v + 1] - 2.0f * d1, 0.0f);
                out[(size_t)b * V_ + v + 1] = sqrtf(sq) * negit;
            }
        }
    }
}

// ---------------------------------------------------------------------------
// Launch: 5 graph nodes total.
// ---------------------------------------------------------------------------
extern "C" void kernel_launch(void* const* d_in, const int* in_sizes, int n_in,
                              void* d_out, int out_size) {
    const int*   ids  = nullptr;
    const float* emb  = nullptr;
    const float* dif  = nullptr;
    const float* traw = nullptr;
    for (int i = 0; i < n_in; i++) {
        switch (in_sizes[i]) {
            case B_ * T_:  ids  = (const int*)d_in[i];   break;
            case V_ * D_:  emb  = (const float*)d_in[i]; break;
            case D_ * D_:  dif  = (const float*)d_in[i]; break;
            case 1:        traw = (const float*)d_in[i]; break;
        }
    }
    float* out = (float*)d_out;

    static bool attr_set = false;
    if (!attr_set) {
        cudaFuncSetAttribute(persist_kernel,
                             cudaFuncAttributeMaxDynamicSharedMemorySize, STEP_SMEM);
        attr_set = true;
    }

    sig_kernel<<<V_, 128>>>(emb);
    zero_kernel<<<(B_ * D_) / 256, 256>>>();
    persist_kernel<<<dim3(8, 16), 512, STEP_SMEM>>>(dif, ids);
    snorm_kernel<<<B_, 32>>>(traw);
    logits_kernel<<<dim3((V_ + 63) / 64, B_ / 32), 128>>>(out);
    (void)out_size;
}